// round 14
// baseline (speedup 1.0000x reference)
#include <cuda_runtime.h>

// B=8, T=2048, V=1024.
// For t = q_j (j-th occurrence of token c in row b), with inclusive prefix
// hist C_v(s) and S_{j-1}[v] = sum_{i<j} C_v(q_i - 1):
//   L_t[v] = w2*( (j-1)*C_v(q_j - 1) - S_{j-1}[v] ) + (w2 + a0)*j*[v==c]
//            + a1*#{i<j : idx(q_i + 1)==v},          out = softmax(L_t).
// k_se (grid 8xB, 150KB smem) builds inclusive per-position prefix rows g_pp
// + CSR occurrence lists. k4_main: ONE WARP PER (b, token) CHAIN — one row
// gather per output row, incremental packed-u16 S, corrections accumulate in
// a warp-private smem bin along the chain. Softmax via ex2 in log2 domain.

namespace {
constexpr int B = 8, T = 2048, V = 1024;
constexpr int NSEG = 64;                    // T/32 segments
constexpr int SE_SMEM =
    NSEG * V * 2      // shist [64][1024] u16
    + T * 2           // srow  [2048] u16
    + V * 2           // soff  [1024] u16
    + 8 * V * 2       // spart [8][1024] u16
    + 16;             // wsum  [4] u32
}

__device__ __align__(16) unsigned short g_pp[B][T][V];     // incl. full prefix
__device__ __align__(16) unsigned short g_row[B][T];
__device__ __align__(16) unsigned short g_off[B][V];       // CSR offsets
__device__ __align__(16) unsigned short g_occ[B][T];       // CSR positions
__device__ __align__(16) unsigned short g_zero[V];         // stays all-zero

__device__ __forceinline__ float ex2(float x) {
    float y;
    asm("ex2.approx.ftz.f32 %0, %1;" : "=f"(y) : "f"(x));
    return y;
}
__device__ __forceinline__ uint4 add4(uint4 a, uint4 b) {
    return make_uint4(a.x + b.x, a.y + b.y, a.z + b.z, a.w + b.w);
}

// ---- K1: setup + expand fused; block (g,b) owns segments 8g..8g+7 ----
__global__ __launch_bounds__(1024) void k_se(const int* __restrict__ idx) {
    extern __shared__ __align__(16) unsigned char smem_raw[];
    unsigned short* const shist = (unsigned short*)smem_raw;     // [64][1024]
    unsigned short* const srow  = shist + NSEG * V;              // [2048]
    unsigned short* const soff  = srow + T;                      // [1024]
    unsigned short* const spart = soff + V;                      // [8][1024]
    unsigned* const wsum = (unsigned*)(spart + 8 * V);           // [4]
    uint4* const shist4 = (uint4*)shist;
    uint4* const spart4 = (uint4*)spart;

    const int g = blockIdx.x, b = blockIdx.y;
    const int tid = threadIdx.x, lane = tid & 31, warp = tid >> 5;
    const int team = tid >> 7, vt = tid & 127;   // team 0..7, uint4 lane 0..127
    const int seg = g * 8 + team;                // this team's segment

    const int2 tt = reinterpret_cast<const int2*>(idx + b * T)[tid];
    srow[2 * tid]     = (unsigned short)tt.x;
    srow[2 * tid + 1] = (unsigned short)tt.y;
    if (g == 0)
        reinterpret_cast<ushort2*>(g_row[b])[tid] =
            make_ushort2((unsigned short)tt.x, (unsigned short)tt.y);

    const uint4 z = make_uint4(0, 0, 0, 0);
    #pragma unroll
    for (int k = 0; k < 8; k++)
        shist4[k * 1024 + tid] = z;
    __syncthreads();

    #pragma unroll
    for (int sg = warp; sg < NSEG; sg += 32) {
        const unsigned tok = srow[sg * 32 + lane];
        const unsigned mask = __match_any_sync(0xffffffffu, tok);
        if ((mask & ((1u << lane) - 1u)) == 0u)
            shist[sg * V + tok] = (unsigned short)__popc(mask);
    }
    __syncthreads();

    uint4 ps = z;
    #pragma unroll
    for (int k = 0; k < 8; k++)
        ps = add4(ps, shist4[(team * 8 + k) * 128 + vt]);
    spart4[team * 128 + vt] = ps;
    __syncthreads();

    uint4 tot = z;
    unsigned exl = 0;
    if (team == 0) {
        #pragma unroll
        for (int tau = 0; tau < 8; tau++)
            tot = add4(tot, spart4[tau * 128 + vt]);
        const unsigned s = tot.x + tot.y + tot.z + tot.w;
        const unsigned t8 = (s & 0xffffu) + (s >> 16);
        unsigned incl = t8;
        #pragma unroll
        for (int o = 1; o < 32; o <<= 1) {
            const unsigned n = __shfl_up_sync(0xffffffffu, incl, o);
            if (lane >= o) incl += n;
        }
        exl = incl - t8;
        if (lane == 31) wsum[warp] = incl;
    }
    __syncthreads();
    if (team == 0) {
        unsigned run = exl;
        #pragma unroll
        for (int ww = 0; ww < 4; ww++)
            if (ww < warp) run += wsum[ww];
        unsigned lanes[8];
        lanes[0] = tot.x & 0xffffu; lanes[1] = tot.x >> 16;
        lanes[2] = tot.y & 0xffffu; lanes[3] = tot.y >> 16;
        lanes[4] = tot.z & 0xffffu; lanes[5] = tot.z >> 16;
        lanes[6] = tot.w & 0xffffu; lanes[7] = tot.w >> 16;
        unsigned offs[8];
        #pragma unroll
        for (int k = 0; k < 8; k++) { offs[k] = run; run += lanes[k]; }
        const uint4 o4 = make_uint4(offs[0] | (offs[1] << 16),
                                    offs[2] | (offs[3] << 16),
                                    offs[4] | (offs[5] << 16),
                                    offs[6] | (offs[7] << 16));
        reinterpret_cast<uint4*>(soff)[vt] = o4;
        if (g == 0)
            reinterpret_cast<uint4*>(&g_off[b][0])[vt] = o4;
    }

    uint4 base = z;
    for (int G = 0; G < g; G++)
        base = add4(base, spart4[G * 128 + vt]);
    for (int k = 0; k < team; k++)
        base = add4(base, shist4[(g * 8 + k) * 128 + vt]);
    __syncthreads();

    shist4[seg * 128 + vt] = base;     // exclusive segment-start counts
    __syncthreads();

    if ((tid & 127) < 32) {            // CSR fill for this segment
        const int s = seg * 32 + lane;
        const unsigned tok = srow[s];
        const unsigned mask = __match_any_sync(0xffffffffu, tok);
        const int rank = __popc(mask & ((1u << lane) - 1u));
        const int slot = (int)soff[tok] + (int)shist[seg * V + tok] + rank;
        g_occ[b][slot] = (unsigned short)s;
    }

    #pragma unroll
    for (int s = 0; s < 32; s++) {     // inclusive prefix rows to g_pp
        const unsigned tok = srow[seg * 32 + s];
        const unsigned u = tok - 8u * (unsigned)vt;
        if (u < 8u) {
            const unsigned inc = 1u << ((u & 1u) << 4);
            const unsigned cj = u >> 1;
            if (cj == 0) base.x += inc;
            else if (cj == 1) base.y += inc;
            else if (cj == 2) base.z += inc;
            else base.w += inc;
        }
        *reinterpret_cast<uint4*>(&g_pp[b][seg * 32 + s][vt * 8]) = base;
    }
}

// ---- warp-local softmax + store (log2-domain logits already in a[32]) ----
__device__ __forceinline__ void softmax_store(float* a, float vmax,
                                              float* orow) {
    #pragma unroll
    for (int o = 16; o; o >>= 1)
        vmax = fmaxf(vmax, __shfl_xor_sync(0xffffffffu, vmax, o));
    float ssum = 0.f;
    #pragma unroll
    for (int k = 0; k < 32; k++) {
        a[k] = ex2(a[k] - vmax);
        ssum += a[k];
    }
    #pragma unroll
    for (int o = 16; o; o >>= 1)
        ssum += __shfl_xor_sync(0xffffffffu, ssum, o);
    const float inv = 1.0f / ssum;
    #pragma unroll
    for (int k = 0; k < 8; k++)
        *reinterpret_cast<float4*>(orow + k * 128) =
            make_float4(a[4 * k] * inv, a[4 * k + 1] * inv,
                        a[4 * k + 2] * inv, a[4 * k + 3] * inv);
}

// ---- K2: main — one warp per (b, token) chain ----
__global__ __launch_bounds__(128, 6) void k4_main(const float* __restrict__ vw,
                                                  float* __restrict__ out) {
    __shared__ float acc[4][V];             // warp-private correction bins
    const int b = blockIdx.y;
    const int tid = threadIdx.x, lane = tid & 31, warp = tid >> 5;
    float* const wacc = acc[warp];
    const int voff = lane * 4;              // lane owns v = k*128 + voff + 0..3

    #pragma unroll
    for (int k = 0; k < 8; k++)
        *reinterpret_cast<float4*>(&wacc[k * 128 + voff]) =
            make_float4(0.f, 0.f, 0.f, 0.f);
    __syncwarp();

    const int c = blockIdx.x * 4 + warp;    // this warp's token
    const unsigned short* const offb = g_off[b];
    const int off0 = offb[c];
    const int off1 = (c < V - 1) ? (int)offb[c + 1] : T;
    const int m = off1 - off0;
    if (m == 0) return;

    const float w0 = vw[0], w1 = vw[1], w2 = vw[2];
    const float L2E = 1.4426950408889634f;
    const float w2s = w2 * L2E;
    const float a1s = (w1 - w2) * L2E;
    const float a0w = (w0 - w2) * L2E + w2s;   // (a0 + w2)*log2e, at v==c
    const unsigned short* const rowb = g_row[b];
    const unsigned short* const occb = g_occ[b];
    const unsigned short* const ppb  = &g_pp[b][0][0];

    if (m <= 32) {
        // ---- fast path: packed u16 running sum S (borrow-free) ----
        unsigned S[16];
        #pragma unroll
        for (int k = 0; k < 16; k++) S[k] = 0u;
        int prev_q = -1;

        for (int j = 1; j <= m; j++) {
            const int q = occb[off0 + j - 1];

            if (lane == 0) {
                atomicAdd(&wacc[c], a0w);                       // (a0+w2)*j term
                if (j >= 2)                                     // bigram entry
                    atomicAdd(&wacc[rowb[prev_q + 1]], a1s);
            }

            // row gather: C(q-1) (zero row for q==0)
            const unsigned short* const rq =
                (q > 0) ? ppb + (size_t)(q - 1) * V : g_zero;
            unsigned R[16];
            #pragma unroll
            for (int k = 0; k < 8; k++) {
                const uint2 u =
                    *reinterpret_cast<const uint2*>(rq + k * 128 + voff);
                R[2 * k]     = u.x;
                R[2 * k + 1] = u.y;
            }
            __syncwarp();                   // corrections visible

            const unsigned jm1 = (unsigned)(j - 1);
            float a[32];
            float vmax = -3.0e38f;
            #pragma unroll
            for (int k = 0; k < 8; k++) {
                const float4 av =
                    *reinterpret_cast<const float4*>(&wacc[k * 128 + voff]);
                const unsigned p0 = jm1 * R[2 * k]     - S[2 * k];
                const unsigned p1 = jm1 * R[2 * k + 1] - S[2 * k + 1];
                S[2 * k]     += R[2 * k];
                S[2 * k + 1] += R[2 * k + 1];
                a[4 * k + 0] = fmaf(w2s, (float)(p0 & 0xffffu), av.x);
                a[4 * k + 1] = fmaf(w2s, (float)(p0 >> 16),     av.y);
                a[4 * k + 2] = fmaf(w2s, (float)(p1 & 0xffffu), av.z);
                a[4 * k + 3] = fmaf(w2s, (float)(p1 >> 16),     av.w);
                vmax = fmaxf(vmax, fmaxf(fmaxf(a[4 * k], a[4 * k + 1]),
                                         fmaxf(a[4 * k + 2], a[4 * k + 3])));
            }
            __syncwarp();                   // reads done before next atomics

            softmax_store(a, vmax, out + (size_t)(b * T + q) * V + voff);
            prev_q = q;
        }
    } else {
        // ---- exact cold path (m > 32): recompute counts per step, i32 ----
        int prev_q = -1;
        #pragma unroll 1
        for (int j = 1; j <= m; j++) {
            const int q = occb[off0 + j - 1];
            if (lane == 0) {
                atomicAdd(&wacc[c], a0w);
                if (j >= 2)
                    atomicAdd(&wacc[rowb[prev_q + 1]], a1s);
            }
            __syncwarp();

            float a[32];
            float vmax = -3.0e38f;
            #pragma unroll 1
            for (int k = 0; k < 8; k++) {
                const float4 av =
                    *reinterpret_cast<const float4*>(&wacc[k * 128 + voff]);
                const uint2 w = *reinterpret_cast<const uint2*>(
                    ppb + (size_t)q * V + k * 128 + voff);   // C(t) inclusive
                int l0 = j * (int)(w.x & 0xffffu);
                int l1 = j * (int)(w.x >> 16);
                int l2 = j * (int)(w.y & 0xffffu);
                int l3 = j * (int)(w.y >> 16);
                for (int i = 1; i <= j; i++) {
                    const int qi = occb[off0 + i - 1];
                    if (qi > 0) {
                        const uint2 u = *reinterpret_cast<const uint2*>(
                            ppb + (size_t)(qi - 1) * V + k * 128 + voff);
                        l0 -= (int)(u.x & 0xffffu); l1 -= (int)(u.x >> 16);
                        l2 -= (int)(u.y & 0xffffu); l3 -= (int)(u.y >> 16);
                    }
                }
                a[4 * k + 0] = fmaf(w2s, (float)l0, av.x);
                a[4 * k + 1] = fmaf(w2s, (float)l1, av.y);
                a[4 * k + 2] = fmaf(w2s, (float)l2, av.z);
                a[4 * k + 3] = fmaf(w2s, (float)l3, av.w);
                vmax = fmaxf(vmax, fmaxf(fmaxf(a[4 * k], a[4 * k + 1]),
                                         fmaxf(a[4 * k + 2], a[4 * k + 3])));
            }
            __syncwarp();

            softmax_store(a, vmax, out + (size_t)(b * T + q) * V + voff);
            prev_q = q;
        }
    }
}

extern "C" void kernel_launch(void* const* d_in, const int* in_sizes, int n_in,
                              void* d_out, int out_size) {
    const int*   idx = (const int*)d_in[0];
    const float* vw  = (const float*)d_in[1];
    float*       out = (float*)d_out;
    (void)in_sizes; (void)n_in; (void)out_size;

    static bool attr_done = false;
    if (!attr_done) {
        cudaFuncSetAttribute(k_se,
                             cudaFuncAttributeMaxDynamicSharedMemorySize,
                             SE_SMEM);
        attr_done = true;
    }

    k_se   <<<dim3(8, B), 1024, SE_SMEM>>>(idx);
    k4_main<<<dim3(V / 4, B), 128>>>(vw, out);
}

// round 15
// speedup vs baseline: 1.1207x; 1.1207x over previous
#include <cuda_runtime.h>

// B=8, T=2048, V=1024.
// c = idx[b,t]; q_1..q_m = occurrences of c in [0..t] (q_m == t); C_v(s) =
// inclusive prefix histogram. Using C(t) = C(t-1) + e_c:
//   L_t[v] = w2*( (m-1)*C_v(t-1) - sum_{j<m} C_v(q_j-1) ) + w0*m*[v==c]
//            + a1*#{j<m : idx(q_j+1)==v},   out = softmax(L_t).
// k_se (grid 8xB, 150KB smem) builds inclusive per-position prefix rows g_pp
// + CSR occurrence lists. k4_main: one warp per t (2 t's/warp), m-1 row
// gathers per t (zero when m==1), packed 2xu16 SIMD, warp-private smem bins,
// evict-first output stores protect g_pp's L2 residency. Softmax via ex2.

namespace {
constexpr int B = 8, T = 2048, V = 1024;
constexpr int NSEG = 64;                    // T/32 segments
constexpr int TPW = 2;                      // t's per warp
constexpr int TPB = 4 * TPW;                // t's per block
constexpr int SE_SMEM =
    NSEG * V * 2      // shist [64][1024] u16
    + T * 2           // srow  [2048] u16
    + V * 2           // soff  [1024] u16
    + 8 * V * 2       // spart [8][1024] u16
    + 16;             // wsum  [4] u32
}

__device__ __align__(16) unsigned short g_pp[B][T][V];     // incl. full prefix
__device__ __align__(16) unsigned short g_row[B][T];
__device__ __align__(16) unsigned short g_off[B][V];       // CSR offsets
__device__ __align__(16) unsigned short g_occ[B][T];       // CSR positions
__device__ __align__(16) unsigned short g_zero[V];         // stays all-zero

__device__ __forceinline__ float ex2(float x) {
    float y;
    asm("ex2.approx.ftz.f32 %0, %1;" : "=f"(y) : "f"(x));
    return y;
}
__device__ __forceinline__ uint4 add4(uint4 a, uint4 b) {
    return make_uint4(a.x + b.x, a.y + b.y, a.z + b.z, a.w + b.w);
}

// ---- K1: setup + expand fused; block (g,b) owns segments 8g..8g+7 ----
__global__ __launch_bounds__(1024) void k_se(const int* __restrict__ idx) {
    extern __shared__ __align__(16) unsigned char smem_raw[];
    unsigned short* const shist = (unsigned short*)smem_raw;     // [64][1024]
    unsigned short* const srow  = shist + NSEG * V;              // [2048]
    unsigned short* const soff  = srow + T;                      // [1024]
    unsigned short* const spart = soff + V;                      // [8][1024]
    unsigned* const wsum = (unsigned*)(spart + 8 * V);           // [4]
    uint4* const shist4 = (uint4*)shist;
    uint4* const spart4 = (uint4*)spart;

    const int g = blockIdx.x, b = blockIdx.y;
    const int tid = threadIdx.x, lane = tid & 31, warp = tid >> 5;
    const int team = tid >> 7, vt = tid & 127;   // team 0..7, uint4 lane 0..127
    const int seg = g * 8 + team;                // this team's segment

    const int2 tt = reinterpret_cast<const int2*>(idx + b * T)[tid];
    srow[2 * tid]     = (unsigned short)tt.x;
    srow[2 * tid + 1] = (unsigned short)tt.y;
    if (g == 0)
        reinterpret_cast<ushort2*>(g_row[b])[tid] =
            make_ushort2((unsigned short)tt.x, (unsigned short)tt.y);

    const uint4 z = make_uint4(0, 0, 0, 0);
    #pragma unroll
    for (int k = 0; k < 8; k++)
        shist4[k * 1024 + tid] = z;
    __syncthreads();

    #pragma unroll
    for (int sg = warp; sg < NSEG; sg += 32) {
        const unsigned tok = srow[sg * 32 + lane];
        const unsigned mask = __match_any_sync(0xffffffffu, tok);
        if ((mask & ((1u << lane) - 1u)) == 0u)
            shist[sg * V + tok] = (unsigned short)__popc(mask);
    }
    __syncthreads();

    uint4 ps = z;
    #pragma unroll
    for (int k = 0; k < 8; k++)
        ps = add4(ps, shist4[(team * 8 + k) * 128 + vt]);
    spart4[team * 128 + vt] = ps;
    __syncthreads();

    uint4 tot = z;
    unsigned exl = 0;
    if (team == 0) {
        #pragma unroll
        for (int tau = 0; tau < 8; tau++)
            tot = add4(tot, spart4[tau * 128 + vt]);
        const unsigned s = tot.x + tot.y + tot.z + tot.w;
        const unsigned t8 = (s & 0xffffu) + (s >> 16);
        unsigned incl = t8;
        #pragma unroll
        for (int o = 1; o < 32; o <<= 1) {
            const unsigned n = __shfl_up_sync(0xffffffffu, incl, o);
            if (lane >= o) incl += n;
        }
        exl = incl - t8;
        if (lane == 31) wsum[warp] = incl;
    }
    __syncthreads();
    if (team == 0) {
        unsigned run = exl;
        #pragma unroll
        for (int ww = 0; ww < 4; ww++)
            if (ww < warp) run += wsum[ww];
        unsigned lanes[8];
        lanes[0] = tot.x & 0xffffu; lanes[1] = tot.x >> 16;
        lanes[2] = tot.y & 0xffffu; lanes[3] = tot.y >> 16;
        lanes[4] = tot.z & 0xffffu; lanes[5] = tot.z >> 16;
        lanes[6] = tot.w & 0xffffu; lanes[7] = tot.w >> 16;
        unsigned offs[8];
        #pragma unroll
        for (int k = 0; k < 8; k++) { offs[k] = run; run += lanes[k]; }
        const uint4 o4 = make_uint4(offs[0] | (offs[1] << 16),
                                    offs[2] | (offs[3] << 16),
                                    offs[4] | (offs[5] << 16),
                                    offs[6] | (offs[7] << 16));
        reinterpret_cast<uint4*>(soff)[vt] = o4;
        if (g == 0)
            reinterpret_cast<uint4*>(&g_off[b][0])[vt] = o4;
    }

    uint4 base = z;
    for (int G = 0; G < g; G++)
        base = add4(base, spart4[G * 128 + vt]);
    for (int k = 0; k < team; k++)
        base = add4(base, shist4[(g * 8 + k) * 128 + vt]);
    __syncthreads();

    shist4[seg * 128 + vt] = base;     // exclusive segment-start counts
    __syncthreads();

    if ((tid & 127) < 32) {            // CSR fill for this segment
        const int s = seg * 32 + lane;
        const unsigned tok = srow[s];
        const unsigned mask = __match_any_sync(0xffffffffu, tok);
        const int rank = __popc(mask & ((1u << lane) - 1u));
        const int slot = (int)soff[tok] + (int)shist[seg * V + tok] + rank;
        g_occ[b][slot] = (unsigned short)s;
    }

    #pragma unroll
    for (int s = 0; s < 32; s++) {     // inclusive prefix rows to g_pp
        const unsigned tok = srow[seg * 32 + s];
        const unsigned u = tok - 8u * (unsigned)vt;
        if (u < 8u) {
            const unsigned inc = 1u << ((u & 1u) << 4);
            const unsigned cj = u >> 1;
            if (cj == 0) base.x += inc;
            else if (cj == 1) base.y += inc;
            else if (cj == 2) base.z += inc;
            else base.w += inc;
        }
        *reinterpret_cast<uint4*>(&g_pp[b][seg * 32 + s][vt * 8]) = base;
    }
}

// ---- K2: main — one warp per t; 4 warps x TPW t's; no block barriers ----
__global__ __launch_bounds__(128, 8) void k4_main(const float* __restrict__ vw,
                                                  float* __restrict__ out) {
    __shared__ float acc[4][V];             // warp-private correction bins
    const int b = blockIdx.y;
    const int t_base = blockIdx.x * TPB;
    const int tid = threadIdx.x, lane = tid & 31, warp = tid >> 5;
    float* const wacc = acc[warp];
    const int voff = lane * 4;              // lane owns v = k*128 + voff + 0..3

    #pragma unroll
    for (int k = 0; k < 8; k++)
        *reinterpret_cast<float4*>(&wacc[k * 128 + voff]) =
            make_float4(0.f, 0.f, 0.f, 0.f);

    const float w0 = vw[0], w1 = vw[1], w2 = vw[2];
    const float L2E = 1.4426950408889634f;  // softmax in log2 domain
    const float w2s = w2 * L2E;
    const float a0s = (w0 - w2) * L2E;      // cold-path coefficient at v==c
    const float a0c = w0 * L2E;             // fast-path coefficient at v==c
    const float a1s = (w1 - w2) * L2E;
    const unsigned short* const rowb = g_row[b];
    const unsigned short* const offb = g_off[b];
    const unsigned short* const occb = g_occ[b];
    const unsigned short* const ppb  = &g_pp[b][0][0];
    __syncwarp();

    for (int i = 0; i < TPW; i++) {
        const int t = t_base + warp * TPW + i;
        const unsigned c = rowb[t];
        const int m = (int)g_pp[b][t][c];   // inclusive count of c at t (>=1)
        const int offc = offb[c];
        const int nq = m - 1;               // prior occurrences (all q < t)
        const bool fast = (m <= 32);        // (m-1)*C <= 31*2048 < 2^16
        const unsigned mul = fast ? (unsigned)nq : 0u;

        // packed 2xu16 SIMD: pa = (m-1)*C(t-1) - sum_{j<m} C(q_j-1)
        unsigned pa[16];
        if (mul != 0u) {
            const unsigned short* const rt1 = ppb + (size_t)(t - 1) * V;
            #pragma unroll
            for (int k = 0; k < 8; k++) {
                const uint2 w =
                    *reinterpret_cast<const uint2*>(rt1 + k * 128 + voff);
                pa[2 * k]     = mul * w.x;
                pa[2 * k + 1] = mul * w.y;
            }
        } else {
            #pragma unroll
            for (int k = 0; k < 16; k++) pa[k] = 0u;
        }

        for (int jb = 0; jb < nq; jb += 32) {
            const int nj = min(32, nq - jb);
            unsigned qv = 0;
            if (lane < nj) qv = occb[offc + jb + lane];
            for (int j = 0; j < nj; j++) {
                const int q = __shfl_sync(0xffffffffu, qv, j);
                if (fast) {
                    const unsigned short* rq =
                        (q > 0) ? ppb + (size_t)(q - 1) * V : g_zero;
                    #pragma unroll
                    for (int k = 0; k < 8; k++) {
                        const uint2 u =
                            *reinterpret_cast<const uint2*>(rq + k * 128 + voff);
                        pa[2 * k]     -= u.x;
                        pa[2 * k + 1] -= u.y;
                    }
                }
                if (lane == 0)              // bigram c -> next token (q < t)
                    atomicAdd(&wacc[rowb[q + 1]], a1s);
            }
        }

        if (!fast) {  // exact cold path (m > 32): i32, overflow-safe
            #pragma unroll 1
            for (int k = 0; k < 8; k++) {
                const uint2 w = *reinterpret_cast<const uint2*>(
                    ppb + (size_t)t * V + k * 128 + voff);   // C(t) inclusive
                int l0 = m * (int)(w.x & 0xffffu);
                int l1 = m * (int)(w.x >> 16);
                int l2 = m * (int)(w.y & 0xffffu);
                int l3 = m * (int)(w.y >> 16);
                for (int j = 0; j < m; j++) {
                    const int q = occb[offc + j];
                    if (q > 0) {
                        const uint2 u = *reinterpret_cast<const uint2*>(
                            ppb + (size_t)(q - 1) * V + k * 128 + voff);
                        l0 -= (int)(u.x & 0xffffu); l1 -= (int)(u.x >> 16);
                        l2 -= (int)(u.y & 0xffffu); l3 -= (int)(u.y >> 16);
                    }
                }
                atomicAdd(&wacc[k * 128 + voff + 0], w2s * (float)l0);
                atomicAdd(&wacc[k * 128 + voff + 1], w2s * (float)l1);
                atomicAdd(&wacc[k * 128 + voff + 2], w2s * (float)l2);
                atomicAdd(&wacc[k * 128 + voff + 3], w2s * (float)l3);
            }
        }

        if (lane == 0)                      // v==c term
            atomicAdd(&wacc[c], (fast ? a0c : a0s) * (float)m);
        __syncwarp();

        // assemble log2-scaled logits, warp-local softmax via EX2
        float a[32];
        float vmax = -3.0e38f;
        #pragma unroll
        for (int k = 0; k < 8; k++) {
            const float4 av =
                *reinterpret_cast<const float4*>(&wacc[k * 128 + voff]);
            *reinterpret_cast<float4*>(&wacc[k * 128 + voff]) =
                make_float4(0.f, 0.f, 0.f, 0.f);  // re-zero for next t
            a[4 * k + 0] = fmaf(w2s, (float)(pa[2 * k] & 0xffffu),     av.x);
            a[4 * k + 1] = fmaf(w2s, (float)(pa[2 * k] >> 16),         av.y);
            a[4 * k + 2] = fmaf(w2s, (float)(pa[2 * k + 1] & 0xffffu), av.z);
            a[4 * k + 3] = fmaf(w2s, (float)(pa[2 * k + 1] >> 16),     av.w);
            vmax = fmaxf(vmax, fmaxf(fmaxf(a[4 * k], a[4 * k + 1]),
                                     fmaxf(a[4 * k + 2], a[4 * k + 3])));
        }
        #pragma unroll
        for (int o = 16; o; o >>= 1)
            vmax = fmaxf(vmax, __shfl_xor_sync(0xffffffffu, vmax, o));

        float ssum = 0.f;
        #pragma unroll
        for (int k = 0; k < 32; k++) {
            a[k] = ex2(a[k] - vmax);
            ssum += a[k];
        }
        #pragma unroll
        for (int o = 16; o; o >>= 1)
            ssum += __shfl_xor_sync(0xffffffffu, ssum, o);
        const float inv = 1.0f / ssum;

        // evict-first stores: don't let the output stream evict g_pp from L2
        float* const orow = out + (size_t)(b * T + t) * V + voff;
        #pragma unroll
        for (int k = 0; k < 8; k++)
            __stcs(reinterpret_cast<float4*>(orow + k * 128),
                   make_float4(a[4 * k] * inv, a[4 * k + 1] * inv,
                               a[4 * k + 2] * inv, a[4 * k + 3] * inv));

        __syncwarp();   // acc re-zero visible before next t's atomics
    }
}

extern "C" void kernel_launch(void* const* d_in, const int* in_sizes, int n_in,
                              void* d_out, int out_size) {
    const int*   idx = (const int*)d_in[0];
    const float* vw  = (const float*)d_in[1];
    float*       out = (float*)d_out;
    (void)in_sizes; (void)n_in; (void)out_size;

    static bool attr_done = false;
    if (!attr_done) {
        cudaFuncSetAttribute(k_se,
                             cudaFuncAttributeMaxDynamicSharedMemorySize,
                             SE_SMEM);
        attr_done = true;
    }

    k_se   <<<dim3(8, B), 1024, SE_SMEM>>>(idx);
    k4_main<<<dim3(T / TPB, B), 128>>>(vw, out);
}

// round 16
// speedup vs baseline: 1.2955x; 1.1559x over previous
#include <cuda_runtime.h>

// B=8, T=2048, V=1024.
// c = idx[b,t]; q_1..q_m = occurrences of c in [0..t]; Cv(r) = inclusive
// prefix histogram:
//   L_t[v] = w2*( m*Cv(t) - sum_j Cv(q_j-1) ) + a0*m*[v==c]
//            + a1*#{j : q_j+1 <= t, idx(q_j+1)==v},   out = softmax(L_t).
// k_se (grid 8xB, 150KB smem): segment hists -> packed uint4 exclusive
// checkpoints g_cp (every 32 positions, 128KB/b — NO full g_pp expand, which
// cost ~7us of pure STG issue) + CSR offsets/occurrence lists.
// k4_main (R6 body, proven 26.1us): one warp per t (2 t's/warp), packed
// 2xu16 SIMD gather over checkpoint rows + 32-lane remainder atomics into
// warp-private smem bins; fused warp-local softmax.

namespace {
constexpr int B = 8, T = 2048, V = 1024;
constexpr int NSEG = 64;                    // T/32 segments
constexpr int TPW = 2;                      // t's per warp
constexpr int TPB = 4 * TPW;                // t's per block
constexpr int SE_SMEM =
    NSEG * V * 2      // shist [64][1024] u16
    + T * 2           // srow  [2048] u16
    + V * 2           // soff  [1024] u16
    + 8 * V * 2       // spart [8][1024] u16
    + 16;             // wsum  [4] u32
}

__device__ __align__(16) unsigned short g_cp[B][NSEG][V];  // excl. seg ckpt
__device__ __align__(16) unsigned short g_row[B][T];
__device__ __align__(16) unsigned short g_off[B][V];       // CSR offsets
__device__ __align__(16) unsigned short g_occ[B][T];       // CSR positions

__device__ __forceinline__ uint4 add4(uint4 a, uint4 b) {
    return make_uint4(a.x + b.x, a.y + b.y, a.z + b.z, a.w + b.w);
}

// ---- K1: setup; block (g,b) owns segments 8g..8g+7 ----
__global__ __launch_bounds__(1024) void k_se(const int* __restrict__ idx) {
    extern __shared__ __align__(16) unsigned char smem_raw[];
    unsigned short* const shist = (unsigned short*)smem_raw;     // [64][1024]
    unsigned short* const srow  = shist + NSEG * V;              // [2048]
    unsigned short* const soff  = srow + T;                      // [1024]
    unsigned short* const spart = soff + V;                      // [8][1024]
    unsigned* const wsum = (unsigned*)(spart + 8 * V);           // [4]
    uint4* const shist4 = (uint4*)shist;
    uint4* const spart4 = (uint4*)spart;

    const int g = blockIdx.x, b = blockIdx.y;
    const int tid = threadIdx.x, lane = tid & 31, warp = tid >> 5;
    const int team = tid >> 7, vt = tid & 127;   // team 0..7, uint4 lane 0..127
    const int seg = g * 8 + team;                // this team's segment

    const int2 tt = reinterpret_cast<const int2*>(idx + b * T)[tid];
    srow[2 * tid]     = (unsigned short)tt.x;
    srow[2 * tid + 1] = (unsigned short)tt.y;
    if (g == 0)
        reinterpret_cast<ushort2*>(g_row[b])[tid] =
            make_ushort2((unsigned short)tt.x, (unsigned short)tt.y);

    const uint4 z = make_uint4(0, 0, 0, 0);
    #pragma unroll
    for (int k = 0; k < 8; k++)
        shist4[k * 1024 + tid] = z;
    __syncthreads();

    #pragma unroll
    for (int sg = warp; sg < NSEG; sg += 32) {
        const unsigned tok = srow[sg * 32 + lane];
        const unsigned mask = __match_any_sync(0xffffffffu, tok);
        if ((mask & ((1u << lane) - 1u)) == 0u)
            shist[sg * V + tok] = (unsigned short)__popc(mask);
    }
    __syncthreads();

    uint4 ps = z;
    #pragma unroll
    for (int k = 0; k < 8; k++)
        ps = add4(ps, shist4[(team * 8 + k) * 128 + vt]);
    spart4[team * 128 + vt] = ps;
    __syncthreads();

    uint4 tot = z;
    unsigned exl = 0;
    if (team == 0) {
        #pragma unroll
        for (int tau = 0; tau < 8; tau++)
            tot = add4(tot, spart4[tau * 128 + vt]);
        const unsigned s = tot.x + tot.y + tot.z + tot.w;
        const unsigned t8 = (s & 0xffffu) + (s >> 16);
        unsigned incl = t8;
        #pragma unroll
        for (int o = 1; o < 32; o <<= 1) {
            const unsigned n = __shfl_up_sync(0xffffffffu, incl, o);
            if (lane >= o) incl += n;
        }
        exl = incl - t8;
        if (lane == 31) wsum[warp] = incl;
    }
    __syncthreads();
    if (team == 0) {
        unsigned run = exl;
        #pragma unroll
        for (int ww = 0; ww < 4; ww++)
            if (ww < warp) run += wsum[ww];
        unsigned lanes[8];
        lanes[0] = tot.x & 0xffffu; lanes[1] = tot.x >> 16;
        lanes[2] = tot.y & 0xffffu; lanes[3] = tot.y >> 16;
        lanes[4] = tot.z & 0xffffu; lanes[5] = tot.z >> 16;
        lanes[6] = tot.w & 0xffffu; lanes[7] = tot.w >> 16;
        unsigned offs[8];
        #pragma unroll
        for (int k = 0; k < 8; k++) { offs[k] = run; run += lanes[k]; }
        const uint4 o4 = make_uint4(offs[0] | (offs[1] << 16),
                                    offs[2] | (offs[3] << 16),
                                    offs[4] | (offs[5] << 16),
                                    offs[6] | (offs[7] << 16));
        reinterpret_cast<uint4*>(soff)[vt] = o4;
        if (g == 0)
            reinterpret_cast<uint4*>(&g_off[b][0])[vt] = o4;
    }

    // exclusive base at the start of this team's segment (packed)
    uint4 base = z;
    for (int G = 0; G < g; G++)
        base = add4(base, spart4[G * 128 + vt]);
    for (int k = 0; k < team; k++)
        base = add4(base, shist4[(g * 8 + k) * 128 + vt]);
    __syncthreads();                 // all base reads done before overwrite

    // publish exclusive segment-start counts: smem (for CSR fill) + g_cp
    shist4[seg * 128 + vt] = base;
    reinterpret_cast<uint4*>(&g_cp[b][seg][0])[vt] = base;   // ONE STG.128
    __syncthreads();

    // CSR fill for this segment (first warp of each team)
    if ((tid & 127) < 32) {
        const int s = seg * 32 + lane;
        const unsigned tok = srow[s];
        const unsigned mask = __match_any_sync(0xffffffffu, tok);
        const int rank = __popc(mask & ((1u << lane) - 1u));
        const int slot = (int)soff[tok] + (int)shist[seg * V + tok] + rank;
        g_occ[b][slot] = (unsigned short)s;
    }
}

// ---- K2: main — R6 body verbatim; one warp per t; no block barriers ----
__global__ __launch_bounds__(128, 8) void k4_main(const float* __restrict__ vw,
                                                  float* __restrict__ out) {
    __shared__ float acc[4][V];             // warp-private bins
    const int b = blockIdx.y;
    const int t_base = blockIdx.x * TPB;    // TPB t's, all in one segment
    const int p = t_base >> 5;
    const int seg0 = p << 5;
    const int tid = threadIdx.x, lane = tid & 31, warp = tid >> 5;
    float* const wacc = acc[warp];
    const int voff = lane * 4;              // lane owns v = k*128 + voff + 0..3

    #pragma unroll
    for (int k = 0; k < 8; k++)
        *reinterpret_cast<float4*>(&wacc[k * 128 + voff]) =
            make_float4(0.f, 0.f, 0.f, 0.f);

    const unsigned stok = g_row[b][seg0 + lane];
    const float w0 = vw[0], w1 = vw[1], w2 = vw[2];
    const float a0 = w0 - w2, a1 = w1 - w2;
    const unsigned short* const cprow_p = &g_cp[b][p][0];
    __syncwarp();

    for (int i = 0; i < TPW; i++) {
        const int t = t_base + warp * TPW + i;
        const int ti = t - seg0;            // 0..31
        const unsigned c = __shfl_sync(0xffffffffu, stok, ti);
        const unsigned ball = __ballot_sync(0xffffffffu, stok == c);
        const int m = (int)g_cp[b][p][c] + __popc(ball & ((2u << ti) - 1u));
        const int offc = g_off[b][c];
        const float fm = (float)m;
        const bool fast = (m <= 31);        // m*CP <= 31*2048 < 2^16
        const unsigned mu = fast ? (unsigned)m : 0u;

        // packed 2xu16 SIMD: pa = m*CP[p] - sum_j CP[(q_j-1)>>5]
        unsigned pa[16];
        #pragma unroll
        for (int k = 0; k < 8; k++) {
            const uint2 w =
                *reinterpret_cast<const uint2*>(cprow_p + k * 128 + voff);
            pa[2 * k]     = mu * w.x;
            pa[2 * k + 1] = mu * w.y;
        }

        for (int jb = 0; jb < m; jb += 32) {
            const int nj = min(32, m - jb);
            unsigned qv = 0;
            if (lane < nj) qv = g_occ[b][offc + jb + lane];
            for (int j = 0; j < nj; j++) {
                const int q = __shfl_sync(0xffffffffu, qv, j);
                if (q > 0) {
                    const int qm1 = q - 1, qp = qm1 >> 5;
                    if (fast) {
                        const unsigned short* rowq = &g_cp[b][qp][0];
                        #pragma unroll
                        for (int k = 0; k < 8; k++) {
                            const uint2 w = *reinterpret_cast<const uint2*>(
                                rowq + k * 128 + voff);
                            pa[2 * k]     -= w.x;
                            pa[2 * k + 1] -= w.y;
                        }
                    }
                    // sub-checkpoint remainder of Cv(q-1)
                    const unsigned rtok = g_row[b][(qp << 5) + lane];
                    if (lane <= (qm1 & 31))
                        atomicAdd(&wacc[rtok], -w2);
                }
                if (q < t && lane == 0)     // bigram c -> next token
                    atomicAdd(&wacc[g_row[b][q + 1]], a1);
            }
        }

        if (!fast) {  // exact cold path for m > 31 (i32, overflow-safe)
            #pragma unroll 1
            for (int k = 0; k < 8; k++) {
                const uint2 w =
                    *reinterpret_cast<const uint2*>(cprow_p + k * 128 + voff);
                int l0 = m * (int)(w.x & 0xffffu);
                int l1 = m * (int)(w.x >> 16);
                int l2 = m * (int)(w.y & 0xffffu);
                int l3 = m * (int)(w.y >> 16);
                for (int j = 0; j < m; j++) {
                    const int q = g_occ[b][offc + j];
                    if (q > 0) {
                        const uint2 u = *reinterpret_cast<const uint2*>(
                            &g_cp[b][(q - 1) >> 5][0] + k * 128 + voff);
                        l0 -= (int)(u.x & 0xffffu); l1 -= (int)(u.x >> 16);
                        l2 -= (int)(u.y & 0xffffu); l3 -= (int)(u.y >> 16);
                    }
                }
                atomicAdd(&wacc[k * 128 + voff + 0], w2 * (float)l0);
                atomicAdd(&wacc[k * 128 + voff + 1], w2 * (float)l1);
                atomicAdd(&wacc[k * 128 + voff + 2], w2 * (float)l2);
                atomicAdd(&wacc[k * 128 + voff + 3], w2 * (float)l3);
            }
        }

        // remainder of Cv(t) over this segment + a0 term
        if (lane <= ti) atomicAdd(&wacc[stok], w2 * fm);
        if (lane == ti) atomicAdd(&wacc[c], a0 * fm);
        __syncwarp();

        // assemble logits (unpack packed counts), warp-local softmax
        float a[32];
        float vmax = -3.0e38f;
        #pragma unroll
        for (int k = 0; k < 8; k++) {
            const float4 av =
                *reinterpret_cast<const float4*>(&wacc[k * 128 + voff]);
            *reinterpret_cast<float4*>(&wacc[k * 128 + voff]) =
                make_float4(0.f, 0.f, 0.f, 0.f);  // re-zero for next t
            a[4 * k + 0] = fmaf(w2, (float)(pa[2 * k] & 0xffffu),     av.x);
            a[4 * k + 1] = fmaf(w2, (float)(pa[2 * k] >> 16),         av.y);
            a[4 * k + 2] = fmaf(w2, (float)(pa[2 * k + 1] & 0xffffu), av.z);
            a[4 * k + 3] = fmaf(w2, (float)(pa[2 * k + 1] >> 16),     av.w);
            vmax = fmaxf(vmax, fmaxf(fmaxf(a[4 * k], a[4 * k + 1]),
                                     fmaxf(a[4 * k + 2], a[4 * k + 3])));
        }
        #pragma unroll
        for (int o = 16; o; o >>= 1)
            vmax = fmaxf(vmax, __shfl_xor_sync(0xffffffffu, vmax, o));

        float ssum = 0.f;
        #pragma unroll
        for (int k = 0; k < 32; k++) {
            a[k] = __expf(a[k] - vmax);
            ssum += a[k];
        }
        #pragma unroll
        for (int o = 16; o; o >>= 1)
            ssum += __shfl_xor_sync(0xffffffffu, ssum, o);
        const float inv = 1.0f / ssum;

        float* const orow = out + (size_t)(b * T + t) * V + voff;
        #pragma unroll
        for (int k = 0; k < 8; k++)
            *reinterpret_cast<float4*>(orow + k * 128) =
                make_float4(a[4 * k] * inv, a[4 * k + 1] * inv,
                            a[4 * k + 2] * inv, a[4 * k + 3] * inv);

        __syncwarp();   // acc re-zero visible before next t's atomics
    }
}

extern "C" void kernel_launch(void* const* d_in, const int* in_sizes, int n_in,
                              void* d_out, int out_size) {
    const int*   idx = (const int*)d_in[0];
    const float* vw  = (const float*)d_in[1];
    float*       out = (float*)d_out;
    (void)in_sizes; (void)n_in; (void)out_size;

    static bool attr_done = false;
    if (!attr_done) {
        cudaFuncSetAttribute(k_se,
                             cudaFuncAttributeMaxDynamicSharedMemorySize,
                             SE_SMEM);
        attr_done = true;
    }

    k_se   <<<dim3(8, B), 1024, SE_SMEM>>>(idx);
    k4_main<<<dim3(T / TPB, B), 128>>>(vw, out);
}

// round 17
// speedup vs baseline: 1.3992x; 1.0800x over previous
#include <cuda_runtime.h>

// B=8, T=2048, V=1024.
// c = idx[b,t]; q_1..q_m = occurrences of c in [0..t]; Cv(r) = inclusive
// prefix histogram:
//   L_t[v] = w2*( m*Cv(t) - sum_j Cv(q_j-1) ) + a0*m*[v==c]
//            + a1*#{j : q_j+1 <= t, idx(q_j+1)==v},   out = softmax(L_t).
// k_se (grid 8xB, 150KB smem): segment hists -> packed uint4 exclusive
// checkpoints g_cp (every 32 positions) + CSR offsets/occurrence lists.
// k4_main: ONE WARP PER T (grid 4096 — fine wave granularity), packed 2xu16
// SIMD gather over checkpoint rows + 32-lane remainder atomics into
// warp-private smem bins; softmax via raw ex2 in log2 domain; sub-word
// cvt.rn.f32.u16 unpack.

namespace {
constexpr int B = 8, T = 2048, V = 1024;
constexpr int NSEG = 64;                    // T/32 segments
constexpr int TPW = 1;                      // t's per warp
constexpr int TPB = 4 * TPW;                // t's per block
constexpr int SE_SMEM =
    NSEG * V * 2      // shist [64][1024] u16
    + T * 2           // srow  [2048] u16
    + V * 2           // soff  [1024] u16
    + 8 * V * 2       // spart [8][1024] u16
    + 16;             // wsum  [4] u32
}

__device__ __align__(16) unsigned short g_cp[B][NSEG][V];  // excl. seg ckpt
__device__ __align__(16) unsigned short g_row[B][T];
__device__ __align__(16) unsigned short g_off[B][V];       // CSR offsets
__device__ __align__(16) unsigned short g_occ[B][T];       // CSR positions

__device__ __forceinline__ uint4 add4(uint4 a, uint4 b) {
    return make_uint4(a.x + b.x, a.y + b.y, a.z + b.z, a.w + b.w);
}
__device__ __forceinline__ float ex2(float x) {
    float y;
    asm("ex2.approx.ftz.f32 %0, %1;" : "=f"(y) : "f"(x));
    return y;
}
// packed u16x2 -> two floats via sub-word I2F (no LOP/SHR extraction)
__device__ __forceinline__ float2 u16x2_to_f32(unsigned p) {
    float lo, hi;
    asm("{ .reg .b16 l, h;\n"
        "  mov.b32 {l, h}, %2;\n"
        "  cvt.rn.f32.u16 %0, l;\n"
        "  cvt.rn.f32.u16 %1, h; }"
        : "=f"(lo), "=f"(hi) : "r"(p));
    return make_float2(lo, hi);
}

// ---- K1: setup; block (g,b) owns segments 8g..8g+7 ----
__global__ __launch_bounds__(1024) void k_se(const int* __restrict__ idx) {
    extern __shared__ __align__(16) unsigned char smem_raw[];
    unsigned short* const shist = (unsigned short*)smem_raw;     // [64][1024]
    unsigned short* const srow  = shist + NSEG * V;              // [2048]
    unsigned short* const soff  = srow + T;                      // [1024]
    unsigned short* const spart = soff + V;                      // [8][1024]
    unsigned* const wsum = (unsigned*)(spart + 8 * V);           // [4]
    uint4* const shist4 = (uint4*)shist;
    uint4* const spart4 = (uint4*)spart;

    const int g = blockIdx.x, b = blockIdx.y;
    const int tid = threadIdx.x, lane = tid & 31, warp = tid >> 5;
    const int team = tid >> 7, vt = tid & 127;   // team 0..7, uint4 lane 0..127
    const int seg = g * 8 + team;                // this team's segment

    const int2 tt = reinterpret_cast<const int2*>(idx + b * T)[tid];
    srow[2 * tid]     = (unsigned short)tt.x;
    srow[2 * tid + 1] = (unsigned short)tt.y;
    if (g == 0)
        reinterpret_cast<ushort2*>(g_row[b])[tid] =
            make_ushort2((unsigned short)tt.x, (unsigned short)tt.y);

    const uint4 z = make_uint4(0, 0, 0, 0);
    #pragma unroll
    for (int k = 0; k < 8; k++)
        shist4[k * 1024 + tid] = z;
    __syncthreads();

    #pragma unroll
    for (int sg = warp; sg < NSEG; sg += 32) {
        const unsigned tok = srow[sg * 32 + lane];
        const unsigned mask = __match_any_sync(0xffffffffu, tok);
        if ((mask & ((1u << lane) - 1u)) == 0u)
            shist[sg * V + tok] = (unsigned short)__popc(mask);
    }
    __syncthreads();

    uint4 ps = z;
    #pragma unroll
    for (int k = 0; k < 8; k++)
        ps = add4(ps, shist4[(team * 8 + k) * 128 + vt]);
    spart4[team * 128 + vt] = ps;
    __syncthreads();

    uint4 tot = z;
    unsigned exl = 0;
    if (team == 0) {
        #pragma unroll
        for (int tau = 0; tau < 8; tau++)
            tot = add4(tot, spart4[tau * 128 + vt]);
        const unsigned s = tot.x + tot.y + tot.z + tot.w;
        const unsigned t8 = (s & 0xffffu) + (s >> 16);
        unsigned incl = t8;
        #pragma unroll
        for (int o = 1; o < 32; o <<= 1) {
            const unsigned n = __shfl_up_sync(0xffffffffu, incl, o);
            if (lane >= o) incl += n;
        }
        exl = incl - t8;
        if (lane == 31) wsum[warp] = incl;
    }
    __syncthreads();
    if (team == 0) {
        unsigned run = exl;
        #pragma unroll
        for (int ww = 0; ww < 4; ww++)
            if (ww < warp) run += wsum[ww];
        unsigned lanes[8];
        lanes[0] = tot.x & 0xffffu; lanes[1] = tot.x >> 16;
        lanes[2] = tot.y & 0xffffu; lanes[3] = tot.y >> 16;
        lanes[4] = tot.z & 0xffffu; lanes[5] = tot.z >> 16;
        lanes[6] = tot.w & 0xffffu; lanes[7] = tot.w >> 16;
        unsigned offs[8];
        #pragma unroll
        for (int k = 0; k < 8; k++) { offs[k] = run; run += lanes[k]; }
        const uint4 o4 = make_uint4(offs[0] | (offs[1] << 16),
                                    offs[2] | (offs[3] << 16),
                                    offs[4] | (offs[5] << 16),
                                    offs[6] | (offs[7] << 16));
        reinterpret_cast<uint4*>(soff)[vt] = o4;
        if (g == 0)
            reinterpret_cast<uint4*>(&g_off[b][0])[vt] = o4;
    }

    uint4 base = z;
    for (int G = 0; G < g; G++)
        base = add4(base, spart4[G * 128 + vt]);
    for (int k = 0; k < team; k++)
        base = add4(base, shist4[(g * 8 + k) * 128 + vt]);
    __syncthreads();                 // all base reads done before overwrite

    shist4[seg * 128 + vt] = base;
    reinterpret_cast<uint4*>(&g_cp[b][seg][0])[vt] = base;   // ONE STG.128
    __syncthreads();

    if ((tid & 127) < 32) {          // CSR fill for this segment
        const int s = seg * 32 + lane;
        const unsigned tok = srow[s];
        const unsigned mask = __match_any_sync(0xffffffffu, tok);
        const int rank = __popc(mask & ((1u << lane) - 1u));
        const int slot = (int)soff[tok] + (int)shist[seg * V + tok] + rank;
        g_occ[b][slot] = (unsigned short)s;
    }
}

// ---- K2: main — one warp per t; 4 t's per block; no block barriers ----
__global__ __launch_bounds__(128, 8) void k4_main(const float* __restrict__ vw,
                                                  float* __restrict__ out) {
    __shared__ float acc[4][V];             // warp-private bins
    const int b = blockIdx.y;
    const int t_base = blockIdx.x * TPB;    // 4 t's, all in one segment
    const int p = t_base >> 5;
    const int seg0 = p << 5;
    const int tid = threadIdx.x, lane = tid & 31, warp = tid >> 5;
    float* const wacc = acc[warp];
    const int voff = lane * 4;              // lane owns v = k*128 + voff + 0..3

    #pragma unroll
    for (int k = 0; k < 8; k++)
        *reinterpret_cast<float4*>(&wacc[k * 128 + voff]) =
            make_float4(0.f, 0.f, 0.f, 0.f);

    const unsigned stok = g_row[b][seg0 + lane];
    const float w0 = vw[0], w1 = vw[1], w2 = vw[2];
    const float L2E = 1.4426950408889634f;  // softmax in log2 domain
    const float w2s = w2 * L2E;
    const float a0s = (w0 - w2) * L2E, a1s = (w1 - w2) * L2E;
    const unsigned short* const cprow_p = &g_cp[b][p][0];
    __syncwarp();

    const int t = t_base + warp;
    const int ti = t - seg0;                // 0..31
    const unsigned c = __shfl_sync(0xffffffffu, stok, ti);
    const unsigned ball = __ballot_sync(0xffffffffu, stok == c);
    const int m = (int)g_cp[b][p][c] + __popc(ball & ((2u << ti) - 1u));
    const int offc = g_off[b][c];
    const float fm = (float)m;
    const bool fast = (m <= 31);            // m*CP <= 31*2048 < 2^16
    const unsigned mu = fast ? (unsigned)m : 0u;

    // packed 2xu16 SIMD: pa = m*CP[p] - sum_j CP[(q_j-1)>>5]
    unsigned pa[16];
    #pragma unroll
    for (int k = 0; k < 8; k++) {
        const uint2 w =
            *reinterpret_cast<const uint2*>(cprow_p + k * 128 + voff);
        pa[2 * k]     = mu * w.x;
        pa[2 * k + 1] = mu * w.y;
    }

    for (int jb = 0; jb < m; jb += 32) {
        const int nj = min(32, m - jb);
        unsigned qv = 0;
        if (lane < nj) qv = g_occ[b][offc + jb + lane];
        for (int j = 0; j < nj; j++) {
            const int q = __shfl_sync(0xffffffffu, qv, j);
            if (q > 0) {
                const int qm1 = q - 1, qp = qm1 >> 5;
                if (fast) {
                    const unsigned short* rowq = &g_cp[b][qp][0];
                    #pragma unroll
                    for (int k = 0; k < 8; k++) {
                        const uint2 w = *reinterpret_cast<const uint2*>(
                            rowq + k * 128 + voff);
                        pa[2 * k]     -= w.x;
                        pa[2 * k + 1] -= w.y;
                    }
                }
                // sub-checkpoint remainder of Cv(q-1)
                const unsigned rtok = g_row[b][(qp << 5) + lane];
                if (lane <= (qm1 & 31))
                    atomicAdd(&wacc[rtok], -w2s);
            }
            if (q < t && lane == 0)         // bigram c -> next token
                atomicAdd(&wacc[g_row[b][q + 1]], a1s);
        }
    }

    if (!fast) {  // exact cold path for m > 31 (i32, overflow-safe)
        #pragma unroll 1
        for (int k = 0; k < 8; k++) {
            const uint2 w =
                *reinterpret_cast<const uint2*>(cprow_p + k * 128 + voff);
            int l0 = m * (int)(w.x & 0xffffu);
            int l1 = m * (int)(w.x >> 16);
            int l2 = m * (int)(w.y & 0xffffu);
            int l3 = m * (int)(w.y >> 16);
            for (int j = 0; j < m; j++) {
                const int q = g_occ[b][offc + j];
                if (q > 0) {
                    const uint2 u = *reinterpret_cast<const uint2*>(
                        &g_cp[b][(q - 1) >> 5][0] + k * 128 + voff);
                    l0 -= (int)(u.x & 0xffffu); l1 -= (int)(u.x >> 16);
                    l2 -= (int)(u.y & 0xffffu); l3 -= (int)(u.y >> 16);
                }
            }
            atomicAdd(&wacc[k * 128 + voff + 0], w2s * (float)l0);
            atomicAdd(&wacc[k * 128 + voff + 1], w2s * (float)l1);
            atomicAdd(&wacc[k * 128 + voff + 2], w2s * (float)l2);
            atomicAdd(&wacc[k * 128 + voff + 3], w2s * (float)l3);
        }
    }

    // remainder of Cv(t) over this segment + a0 term
    if (lane <= ti) atomicAdd(&wacc[stok], w2s * fm);
    if (lane == ti) atomicAdd(&wacc[c], a0s * fm);
    __syncwarp();

    // assemble log2-scaled logits (sub-word I2F unpack), softmax via EX2
    float a[32];
    float vmax = -3.0e38f;
    #pragma unroll
    for (int k = 0; k < 8; k++) {
        const float4 av =
            *reinterpret_cast<const float4*>(&wacc[k * 128 + voff]);
        const float2 f0 = u16x2_to_f32(pa[2 * k]);
        const float2 f1 = u16x2_to_f32(pa[2 * k + 1]);
        a[4 * k + 0] = fmaf(w2s, f0.x, av.x);
        a[4 * k + 1] = fmaf(w2s, f0.y, av.y);
        a[4 * k + 2] = fmaf(w2s, f1.x, av.z);
        a[4 * k + 3] = fmaf(w2s, f1.y, av.w);
        vmax = fmaxf(vmax, fmaxf(fmaxf(a[4 * k], a[4 * k + 1]),
                                 fmaxf(a[4 * k + 2], a[4 * k + 3])));
    }
    #pragma unroll
    for (int o = 16; o; o >>= 1)
        vmax = fmaxf(vmax, __shfl_xor_sync(0xffffffffu, vmax, o));

    float ssum = 0.f;
    #pragma unroll
    for (int k = 0; k < 32; k++) {
        a[k] = ex2(a[k] - vmax);
        ssum += a[k];
    }
    #pragma unroll
    for (int o = 16; o; o >>= 1)
        ssum += __shfl_xor_sync(0xffffffffu, ssum, o);
    const float inv = 1.0f / ssum;

    float* const orow = out + (size_t)(b * T + t) * V + voff;
    #pragma unroll
    for (int k = 0; k < 8; k++)
        *reinterpret_cast<float4*>(orow + k * 128) =
            make_float4(a[4 * k] * inv, a[4 * k + 1] * inv,
                        a[4 * k + 2] * inv, a[4 * k + 3] * inv);
}

extern "C" void kernel_launch(void* const* d_in, const int* in_sizes, int n_in,
                              void* d_out, int out_size) {
    const int*   idx = (const int*)d_in[0];
    const float* vw  = (const float*)d_in[1];
    float*       out = (float*)d_out;
    (void)in_sizes; (void)n_in; (void)out_size;

    static bool attr_done = false;
    if (!attr_done) {
        cudaFuncSetAttribute(k_se,
                             cudaFuncAttributeMaxDynamicSharedMemorySize,
                             SE_SMEM);
        attr_done = true;
    }

    k_se   <<<dim3(8, B), 1024, SE_SMEM>>>(idx);
    k4_main<<<dim3(T / TPB, B), 128>>>(vw, out);
}